// round 7
// baseline (speedup 1.0000x reference)
#include <cuda_runtime.h>
#include <cuda_fp16.h>
#include <math.h>

#define B_  32
#define P_  16384
#define J_  10
#define O_  16
#define JO_ 160

// Scratch (device globals: no allocation allowed in kernel_launch)
__device__ unsigned short g_uh[(size_t)B_ * P_ * JO_]; // 168MB fp16 u_hat[b][p][jo]
__device__ float g_xT[(size_t)P_ * 8 * B_];            // 16MB x transposed [p][d][b]
__device__ float g_s[3 * B_ * JO_];                    // s accumulators
__device__ float g_vf[B_ * JO_];                       // v1 stash (fp32)
__device__ unsigned short g_vh[B_ * JO_];              // current dot-vector (fp16)

// Packed fp32 FMA / ADD (f32x2): exact fp32 math, 2 lanes per instruction.
__device__ __forceinline__ float2 ffma2(float2 a, float2 b, float2 c) {
    unsigned long long A = *reinterpret_cast<unsigned long long*>(&a);
    unsigned long long Bv = *reinterpret_cast<unsigned long long*>(&b);
    unsigned long long C = *reinterpret_cast<unsigned long long*>(&c);
    unsigned long long D;
    asm("fma.rn.f32x2 %0, %1, %2, %3;" : "=l"(D) : "l"(A), "l"(Bv), "l"(C));
    return *reinterpret_cast<float2*>(&D);
}
__device__ __forceinline__ float2 fadd2(float2 a, float2 b) {
    unsigned long long A = *reinterpret_cast<unsigned long long*>(&a);
    unsigned long long Bv = *reinterpret_cast<unsigned long long*>(&b);
    unsigned long long D;
    asm("add.rn.f32x2 %0, %1, %2;" : "=l"(D) : "l"(A), "l"(Bv));
    return *reinterpret_cast<float2*>(&D);
}
__device__ __forceinline__ float2 dup2(float x) { return make_float2(x, x); }

// ---------------------------------------------------------------------------
// Prep: transpose x (b,p,d) -> xT[(p*8+d)*32+b], and zero g_s.
// Grid exactly covers 4,194,304 elements (16384 blocks x 256).
// ---------------------------------------------------------------------------
__global__ void prep_kernel(const float* __restrict__ x) {
    const int i = blockIdx.x * 256 + threadIdx.x;
    if (i < 3 * B_ * JO_) g_s[i] = 0.f;
    const int b = i & 31;
    const int rest = i >> 5;
    const int d = rest & 7;
    const int p = rest >> 3;
    g_xT[i] = x[((size_t)b * P_ + p) * 8 + d];
}

// ---------------------------------------------------------------------------
// Pass 0: u_hat[b,p,jo] = sum_d x[b,p,d] * W[j,p,d,o]   (fp16 out)
// Warp = b-quartet (w*4) x 2 p per iteration. Lane unit u = r*32+lane:
//   psub = u>=80 (which p of the pair), h = (2u)%160 = jo-pair base.
// x comes from xT via uniform-address LDG.128 broadcasts (NO shuffles).
// W read as float2 (LDG.64, L1-cached across the 8 quartet warps).
// FMA via fma.rn.f32x2; u_hat stored streaming (st.global.cs).
// s1 partials in per-warp smem slices (4b x 160, f32x2 RMW, 2 psub phases),
// folded to global atomics once per block.
// ---------------------------------------------------------------------------
#define NP 16
__global__ __launch_bounds__(256, 3) void pass0_kernel(const float* __restrict__ W) {
    const int w    = threadIdx.x >> 5;
    const int lane = threadIdx.x & 31;
    const int b0   = w * 4;
    const int pbase = blockIdx.x * NP;       // 1024 blocks

    __shared__ float s1sm[8][4 * JO_];       // 20KB: per-warp quartet slices
    float* s1w = s1sm[w];
    for (int i = lane; i < 4 * JO_; i += 32) s1w[i] = 0.f;
    __syncwarp();

    // unit geometry (r=0,1 -> psub 0; r=3,4 -> psub 1; r=2 lane-split)
    int h[5], ps[5], woff[5];
#pragma unroll
    for (int r = 0; r < 5; r++) {
        const int u = r * 32 + lane;
        ps[r] = (u >= 80) ? 1 : 0;
        h[r]  = (2 * u) % 160;
        woff[r] = (h[r] >> 4) * (P_ * 128) + ps[r] * 128 + (h[r] & 15);
    }

    __half* uh = reinterpret_cast<__half*>(g_uh);

    for (int it = 0; it < NP / 2; it++) {
        const int p0 = pbase + it * 2;
        const float* xA = g_xT + p0 * 256 + b0;    // d stride 32, psub stride 256
        const float* Wq = W + (size_t)p0 * 128;

        float2 acc[4][5];
#pragma unroll
        for (int bb = 0; bb < 4; bb++)
#pragma unroll
            for (int r = 0; r < 5; r++) acc[bb][r] = make_float2(0.f, 0.f);

#pragma unroll
        for (int d = 0; d < 8; d++) {
            const float4 x0 = *(const float4*)(xA + d * 32);        // psub 0, b0..b0+3
            const float4 x1 = *(const float4*)(xA + 256 + d * 32);  // psub 1
            float2 wv[5];
#pragma unroll
            for (int r = 0; r < 5; r++)
                wv[r] = __ldg((const float2*)(Wq + woff[r] + d * 16));

#define DO_BB(bb, c0, c1)                                                     \
            {                                                                 \
                const float xs0 = (c0), xs1 = (c1);                           \
                const float xsC = (lane & 16) ? xs1 : xs0;                    \
                acc[bb][0] = ffma2(dup2(xs0), wv[0], acc[bb][0]);             \
                acc[bb][1] = ffma2(dup2(xs0), wv[1], acc[bb][1]);             \
                acc[bb][2] = ffma2(dup2(xsC), wv[2], acc[bb][2]);             \
                acc[bb][3] = ffma2(dup2(xs1), wv[3], acc[bb][3]);             \
                acc[bb][4] = ffma2(dup2(xs1), wv[4], acc[bb][4]);             \
            }
            DO_BB(0, x0.x, x1.x)
            DO_BB(1, x0.y, x1.y)
            DO_BB(2, x0.z, x1.z)
            DO_BB(3, x0.w, x1.w)
#undef DO_BB
        }

        // streaming stores (half2)
#pragma unroll
        for (int bb = 0; bb < 4; bb++) {
            __half* base = uh + ((size_t)(b0 + bb) * P_ + p0) * JO_;
#pragma unroll
            for (int r = 0; r < 5; r++) {
                __half2 hv = __float22half2_rn(acc[bb][r]);
                __stcs((unsigned*)(base + ps[r] * JO_ + h[r]),
                       *reinterpret_cast<unsigned*>(&hv));
            }
        }

        // s1 smem accumulation: 2 race-free psub phases
#pragma unroll
        for (int ph = 0; ph < 2; ph++) {
#pragma unroll
            for (int r = 0; r < 5; r++) {
                if (ps[r] == ph) {
#pragma unroll
                    for (int bb = 0; bb < 4; bb++) {
                        float2* sp = (float2*)&s1w[bb * JO_ + h[r]];
                        *sp = fadd2(*sp, acc[bb][r]);
                    }
                }
            }
            __syncwarp();
        }
    }

    __syncthreads();
    // fold: each (b,jo) lives in exactly one warp slice
    for (int i = threadIdx.x; i < B_ * JO_; i += 256) {
        const int b = i / JO_, jo = i % JO_;
        atomicAdd(&g_s[i], s1sm[b >> 2][(b & 3) * JO_ + jo] * 0.1f);
    }
}

// ---------------------------------------------------------------------------
// Squash: v = s * sqrt(|s|^2) / (1 + |s|^2). One thread per (b,j).
// phase 0: v1 -> g_vh (fp16) and g_vf (fp32 stash)
// phase 1: v2 -> g_vh = fp16(v1 + v2)    [logit linearity: b = u·(v1+v2)]
// phase 2: v3 -> d_out (fp32)
// ---------------------------------------------------------------------------
__global__ void squash_kernel(int phase, float* dout) {
    int t = blockIdx.x * blockDim.x + threadIdx.x;
    if (t >= B_ * J_) return;
    const float* sp = g_s + phase * B_ * JO_ + t * O_;
    float sv[16], sq = 0.f;
#pragma unroll
    for (int o = 0; o < 16; o++) { sv[o] = sp[o]; sq += sv[o] * sv[o]; }
    const float scale = sqrtf(sq) / (1.f + sq);
    __half* vh = reinterpret_cast<__half*>(g_vh) + t * O_;
    if (phase == 0) {
#pragma unroll
        for (int o = 0; o < 16; o++) {
            const float v = sv[o] * scale;
            g_vf[t * O_ + o] = v;
            vh[o] = __float2half(v);
        }
    } else if (phase == 1) {
#pragma unroll
        for (int o = 0; o < 16; o++)
            vh[o] = __float2half(g_vf[t * O_ + o] + sv[o] * scale);
    } else {
#pragma unroll
        for (int o = 0; o < 16; o++) dout[t * O_ + o] = sv[o] * scale;
    }
}

// ---------------------------------------------------------------------------
// Fused routing pass: 4 p per iteration, prefetched streaming uint2 loads.
// Unit u = r*32+lane: psub = u/40, slot = u>>2 = psub*10+j.
// Dot: 4-wide fp16 product + 2 shfl quad-reduce. Softmax per octet. No g_b.
// c*u accumulate via fma.rn.f32x2.
// ---------------------------------------------------------------------------
template <int SLOT>
__global__ __launch_bounds__(256) void route_kernel() {
    const int w     = threadIdx.x >> 5;
    const int lane  = threadIdx.x & 31;
    const int gw    = blockIdx.x * 8 + w;     // 16384 warps
    const int b     = gw >> 9;
    const int pbase = (gw & 511) << 5;        // 32 p per warp

    __shared__ float gbuf[8][40];
    __shared__ float cbuf[8][40];
    __shared__ float red[8][JO_];

    uint2 v2[5];
#pragma unroll
    for (int r = 0; r < 5; r++) {
        const int qq = (4 * (r * 32 + lane)) % 160;
        v2[r] = *(const uint2*)(g_vh + b * JO_ + qq);
    }

    float2 sacc[5][2];
#pragma unroll
    for (int r = 0; r < 5; r++) {
        sacc[r][0] = make_float2(0.f, 0.f);
        sacc[r][1] = make_float2(0.f, 0.f);
    }

    const uint2* up = (const uint2*)(g_uh + ((size_t)b * P_ + pbase) * JO_);

    // softmax ownership: octet = p_sub (lane>>3), k8 = lane&7
    const int sm_ps = lane >> 3;
    const int k8    = lane & 7;
    const int nj    = (k8 < 2) ? 2 : 1;       // j in {k8, k8+8?}

    uint2 ucur[5], unxt[5];
#pragma unroll
    for (int r = 0; r < 5; r++) ucur[r] = __ldcs(up + r * 32 + lane);

    for (int it = 0; it < 8; it++) {
        if (it < 7) {
#pragma unroll
            for (int r = 0; r < 5; r++)
                unxt[r] = __ldcs(up + (it + 1) * 160 + r * 32 + lane);
        }

        // dots: per-unit 4-wide fp16 product, fp32 quad reduction
#pragma unroll
        for (int r = 0; r < 5; r++) {
            const __half2* uh2 = (const __half2*)&ucur[r];
            const __half2* vh2 = (const __half2*)&v2[r];
            const __half2 t = __hfma2(uh2[0], vh2[0], __hmul2(uh2[1], vh2[1]));
            float dv = __low2float(t) + __high2float(t);
            dv += __shfl_xor_sync(0xffffffffu, dv, 1);
            dv += __shfl_xor_sync(0xffffffffu, dv, 2);
            if ((lane & 3) == 0) gbuf[w][r * 8 + (lane >> 2)] = dv;
        }
        __syncwarp();

        // softmax over j for the 4 p's (octet-local)
        {
            float lg[2];
            float mx = -1e30f;
#pragma unroll
            for (int i = 0; i < 2; i++) {
                if (i < nj) {
                    lg[i] = gbuf[w][sm_ps * 10 + k8 + i * 8];
                    mx = fmaxf(mx, lg[i]);
                } else lg[i] = -1e30f;
            }
            mx = fmaxf(mx, __shfl_xor_sync(0xffffffffu, mx, 1));
            mx = fmaxf(mx, __shfl_xor_sync(0xffffffffu, mx, 2));
            mx = fmaxf(mx, __shfl_xor_sync(0xffffffffu, mx, 4));
            float e[2], sm = 0.f;
#pragma unroll
            for (int i = 0; i < 2; i++) {
                e[i] = (i < nj) ? __expf(lg[i] - mx) : 0.f;
                sm += e[i];
            }
            sm += __shfl_xor_sync(0xffffffffu, sm, 1);
            sm += __shfl_xor_sync(0xffffffffu, sm, 2);
            sm += __shfl_xor_sync(0xffffffffu, sm, 4);
            const float inv = __fdividef(1.f, sm);
#pragma unroll
            for (int i = 0; i < 2; i++)
                if (i < nj) cbuf[w][sm_ps * 10 + k8 + i * 8] = e[i] * inv;
        }
        __syncwarp();

        // accumulate c * u (packed fp32 FMA)
#pragma unroll
        for (int r = 0; r < 5; r++) {
            const float2 c2 = dup2(cbuf[w][r * 8 + (lane >> 2)]);
            const __half2* uh2 = (const __half2*)&ucur[r];
            sacc[r][0] = ffma2(c2, __half22float2(uh2[0]), sacc[r][0]);
            sacc[r][1] = ffma2(c2, __half22float2(uh2[1]), sacc[r][1]);
        }
        __syncwarp();

#pragma unroll
        for (int r = 0; r < 5; r++) ucur[r] = unxt[r];
    }

    // fold sacc into red[w][jo]: 4 phases by p_sub (conflict-free per phase)
    for (int i = lane; i < JO_; i += 32) red[w][i] = 0.f;
    __syncwarp();
#pragma unroll
    for (int ph = 0; ph < 4; ph++) {
#pragma unroll
        for (int r = 0; r < 5; r++) {
            const int u = r * 32 + lane;
            if (u / 40 == ph) {
                const int qq = (4 * u) % 160;
                red[w][qq + 0] += sacc[r][0].x;
                red[w][qq + 1] += sacc[r][0].y;
                red[w][qq + 2] += sacc[r][1].x;
                red[w][qq + 3] += sacc[r][1].y;
            }
        }
        __syncwarp();
    }
    __syncthreads();

    if (threadIdx.x < JO_) {
        float s = 0.f;
#pragma unroll
        for (int k = 0; k < 8; k++) s += red[k][threadIdx.x];
        atomicAdd(&g_s[SLOT * B_ * JO_ + b * JO_ + threadIdx.x], s);
    }
}

// ---------------------------------------------------------------------------
extern "C" void kernel_launch(void* const* d_in, const int* in_sizes, int n_in,
                              void* d_out, int out_size) {
    const float* x = (const float*)d_in[0];
    const float* W = (const float*)d_in[1];
    if (n_in >= 2 && in_sizes[0] > in_sizes[1]) {
        x = (const float*)d_in[1];
        W = (const float*)d_in[0];
    }
    float* out = (float*)d_out;

    prep_kernel<<<16384, 256>>>(x);            // xT transpose + zero g_s
    pass0_kernel<<<1024, 256>>>(W);            // u_hat + s1
    squash_kernel<<<2, 160>>>(0, nullptr);     // v1 -> g_vh, g_vf
    route_kernel<1><<<2048, 256>>>();          // logits u·v1 -> s2
    squash_kernel<<<2, 160>>>(1, nullptr);     // g_vh = v1+v2
    route_kernel<2><<<2048, 256>>>();          // logits u·(v1+v2) -> s3
    squash_kernel<<<2, 160>>>(2, out);         // v3 -> out
}

// round 8
// speedup vs baseline: 1.1499x; 1.1499x over previous
#include <cuda_runtime.h>
#include <cuda_fp16.h>
#include <math.h>

#define B_  32
#define P_  16384
#define J_  10
#define O_  16
#define JO_ 160

// Scratch (device globals: no allocation allowed in kernel_launch)
__device__ unsigned short g_uh[(size_t)B_ * P_ * JO_]; // 168MB fp16 u_hat[b][p][jo]
__device__ float g_s[3 * B_ * JO_];                    // s accumulators
__device__ float g_vf[B_ * JO_];                       // v1 stash (fp32)
__device__ unsigned short g_vh[B_ * JO_];              // current dot-vector (fp16)

// Packed fp32 FMA / ADD (f32x2): exact fp32 math, 2 lanes per instruction.
__device__ __forceinline__ float2 ffma2(float2 a, float2 b, float2 c) {
    unsigned long long A = *reinterpret_cast<unsigned long long*>(&a);
    unsigned long long Bv = *reinterpret_cast<unsigned long long*>(&b);
    unsigned long long C = *reinterpret_cast<unsigned long long*>(&c);
    unsigned long long D;
    asm("fma.rn.f32x2 %0, %1, %2, %3;" : "=l"(D) : "l"(A), "l"(Bv), "l"(C));
    return *reinterpret_cast<float2*>(&D);
}
__device__ __forceinline__ float2 fadd2(float2 a, float2 b) {
    unsigned long long A = *reinterpret_cast<unsigned long long*>(&a);
    unsigned long long Bv = *reinterpret_cast<unsigned long long*>(&b);
    unsigned long long D;
    asm("add.rn.f32x2 %0, %1, %2;" : "=l"(D) : "l"(A), "l"(Bv));
    return *reinterpret_cast<float2*>(&D);
}
__device__ __forceinline__ float2 dup2(float x) { return make_float2(x, x); }

// ---------------------------------------------------------------------------
__global__ void zero_s_kernel() {
    int i = blockIdx.x * blockDim.x + threadIdx.x;
    if (i < 3 * B_ * JO_) g_s[i] = 0.f;
}

// ---------------------------------------------------------------------------
// Pass 0: u_hat[b,p,jo] = sum_d x[b,p,d] * W[j,p,d,o]   (fp16 out)
// Block = 16 p x all 32 b. Warp = b-quartet (b0 = w*4), 2 p per iteration.
// x tile (16 KB) cooperatively staged in smem [e=p'*8+d][b] -> inner loop
// reads it via uniform-address LDS.128 broadcast (no shuffles, no transpose
// kernel, coalesced global reads).
// Lane unit u = r*32+lane: psub = u>=80, h = (2u)%160 = jo-pair base.
// W read as float2 (LDG.64, L1-shared across the 8 warps covering the same p).
// FMA via fma.rn.f32x2; u_hat stored streaming (st.global.cs).
// s1 partials in per-warp smem slices, folded to global atomics once.
// ---------------------------------------------------------------------------
#define NP 16
__global__ __launch_bounds__(256) void pass0_kernel(const float* __restrict__ x,
                                                    const float* __restrict__ W) {
    const int w    = threadIdx.x >> 5;
    const int lane = threadIdx.x & 31;
    const int b0   = w * 4;
    const int pbase = blockIdx.x * NP;       // 1024 blocks

    __shared__ float xs[NP * 8 * B_];        // 16KB: [e][b], e = p'*8+d
    __shared__ float s1sm[8][4 * JO_];       // 20KB: per-warp quartet slices

    // cooperative coalesced x tile load: thread = (b, 16-float chunk)
    {
        const int tb = threadIdx.x >> 3;
        const int tc = threadIdx.x & 7;
        const float* xp = x + ((size_t)tb * P_ + pbase) * 8 + tc * 16;
#pragma unroll
        for (int k = 0; k < 16; k++)
            xs[(tc * 16 + k) * B_ + tb] = xp[k];
    }
    float* s1w = s1sm[w];
    for (int i = lane; i < 4 * JO_; i += 32) s1w[i] = 0.f;
    __syncthreads();

    // unit geometry (r=0,1 -> psub 0; r=3,4 -> psub 1; r=2 lane-split)
    int h[5], ps[5], woff[5];
#pragma unroll
    for (int r = 0; r < 5; r++) {
        const int u = r * 32 + lane;
        ps[r] = (u >= 80) ? 1 : 0;
        h[r]  = (2 * u) % 160;
        woff[r] = (h[r] >> 4) * (P_ * 128) + ps[r] * 128 + (h[r] & 15);
    }

    __half* uh = reinterpret_cast<__half*>(g_uh);

    for (int it = 0; it < NP / 2; it++) {
        const int p0 = pbase + it * 2;
        const float* xA = xs + (it * 16) * B_ + b0;   // d stride 32, psub stride 256
        const float* Wq = W + (size_t)p0 * 128;

        float2 acc[4][5];
#pragma unroll
        for (int bb = 0; bb < 4; bb++)
#pragma unroll
            for (int r = 0; r < 5; r++) acc[bb][r] = make_float2(0.f, 0.f);

#pragma unroll
        for (int d = 0; d < 8; d++) {
            const float4 x0 = *(const float4*)(xA + d * B_);            // psub 0
            const float4 x1 = *(const float4*)(xA + 8 * B_ + d * B_);   // psub 1
            float2 wv[5];
#pragma unroll
            for (int r = 0; r < 5; r++)
                wv[r] = __ldg((const float2*)(Wq + woff[r] + d * 16));

#define DO_BB(bb, c0, c1)                                                     \
            {                                                                 \
                const float xs0 = (c0), xs1 = (c1);                           \
                const float xsC = (lane & 16) ? xs1 : xs0;                    \
                acc[bb][0] = ffma2(dup2(xs0), wv[0], acc[bb][0]);             \
                acc[bb][1] = ffma2(dup2(xs0), wv[1], acc[bb][1]);             \
                acc[bb][2] = ffma2(dup2(xsC), wv[2], acc[bb][2]);             \
                acc[bb][3] = ffma2(dup2(xs1), wv[3], acc[bb][3]);             \
                acc[bb][4] = ffma2(dup2(xs1), wv[4], acc[bb][4]);             \
            }
            DO_BB(0, x0.x, x1.x)
            DO_BB(1, x0.y, x1.y)
            DO_BB(2, x0.z, x1.z)
            DO_BB(3, x0.w, x1.w)
#undef DO_BB
        }

        // streaming stores (half2)
#pragma unroll
        for (int bb = 0; bb < 4; bb++) {
            __half* base = uh + ((size_t)(b0 + bb) * P_ + p0) * JO_;
#pragma unroll
            for (int r = 0; r < 5; r++) {
                __half2 hv = __float22half2_rn(acc[bb][r]);
                __stcs((unsigned*)(base + ps[r] * JO_ + h[r]),
                       *reinterpret_cast<unsigned*>(&hv));
            }
        }

        // s1 smem accumulation: 2 race-free psub phases
#pragma unroll
        for (int ph = 0; ph < 2; ph++) {
#pragma unroll
            for (int r = 0; r < 5; r++) {
                if (ps[r] == ph) {
#pragma unroll
                    for (int bb = 0; bb < 4; bb++) {
                        float2* sp = (float2*)&s1w[bb * JO_ + h[r]];
                        *sp = fadd2(*sp, acc[bb][r]);
                    }
                }
            }
            __syncwarp();
        }
    }

    __syncthreads();
    // fold: each (b,jo) lives in exactly one warp slice
    for (int i = threadIdx.x; i < B_ * JO_; i += 256) {
        const int b = i / JO_, jo = i % JO_;
        atomicAdd(&g_s[i], s1sm[b >> 2][(b & 3) * JO_ + jo] * 0.1f);
    }
}

// ---------------------------------------------------------------------------
// Squash: v = s * sqrt(|s|^2) / (1 + |s|^2). One thread per (b,j).
// phase 0: v1 -> g_vh (fp16) and g_vf (fp32 stash)
// phase 1: v2 -> g_vh = fp16(v1 + v2)    [logit linearity: b = u·(v1+v2)]
// phase 2: v3 -> d_out (fp32)
// ---------------------------------------------------------------------------
__global__ void squash_kernel(int phase, float* dout) {
    int t = blockIdx.x * blockDim.x + threadIdx.x;
    if (t >= B_ * J_) return;
    const float* sp = g_s + phase * B_ * JO_ + t * O_;
    float sv[16], sq = 0.f;
#pragma unroll
    for (int o = 0; o < 16; o++) { sv[o] = sp[o]; sq += sv[o] * sv[o]; }
    const float scale = sqrtf(sq) / (1.f + sq);
    __half* vh = reinterpret_cast<__half*>(g_vh) + t * O_;
    if (phase == 0) {
#pragma unroll
        for (int o = 0; o < 16; o++) {
            const float v = sv[o] * scale;
            g_vf[t * O_ + o] = v;
            vh[o] = __float2half(v);
        }
    } else if (phase == 1) {
#pragma unroll
        for (int o = 0; o < 16; o++)
            vh[o] = __float2half(g_vf[t * O_ + o] + sv[o] * scale);
    } else {
#pragma unroll
        for (int o = 0; o < 16; o++) dout[t * O_ + o] = sv[o] * scale;
    }
}

// ---------------------------------------------------------------------------
// Fused routing pass: 4 p per iteration, prefetched streaming uint2 loads.
// Unit u = r*32+lane: psub = u/40, slot = u>>2 = psub*10+j.
// Dot: 4-wide fp16 product + 2 shfl quad-reduce. Softmax per octet. No g_b.
// c*u accumulate via fma.rn.f32x2.
// ---------------------------------------------------------------------------
template <int SLOT>
__global__ __launch_bounds__(256) void route_kernel() {
    const int w     = threadIdx.x >> 5;
    const int lane  = threadIdx.x & 31;
    const int gw    = blockIdx.x * 8 + w;     // 16384 warps
    const int b     = gw >> 9;
    const int pbase = (gw & 511) << 5;        // 32 p per warp

    __shared__ float gbuf[8][40];
    __shared__ float cbuf[8][40];
    __shared__ float red[8][JO_];

    uint2 v2[5];
#pragma unroll
    for (int r = 0; r < 5; r++) {
        const int qq = (4 * (r * 32 + lane)) % 160;
        v2[r] = *(const uint2*)(g_vh + b * JO_ + qq);
    }

    float2 sacc[5][2];
#pragma unroll
    for (int r = 0; r < 5; r++) {
        sacc[r][0] = make_float2(0.f, 0.f);
        sacc[r][1] = make_float2(0.f, 0.f);
    }

    const uint2* up = (const uint2*)(g_uh + ((size_t)b * P_ + pbase) * JO_);

    // softmax ownership: octet = p_sub (lane>>3), k8 = lane&7
    const int sm_ps = lane >> 3;
    const int k8    = lane & 7;
    const int nj    = (k8 < 2) ? 2 : 1;       // j in {k8, k8+8?}

    uint2 ucur[5], unxt[5];
#pragma unroll
    for (int r = 0; r < 5; r++) ucur[r] = __ldcs(up + r * 32 + lane);

    for (int it = 0; it < 8; it++) {
        if (it < 7) {
#pragma unroll
            for (int r = 0; r < 5; r++)
                unxt[r] = __ldcs(up + (it + 1) * 160 + r * 32 + lane);
        }

        // dots: per-unit 4-wide fp16 product, fp32 quad reduction
#pragma unroll
        for (int r = 0; r < 5; r++) {
            const __half2* uh2 = (const __half2*)&ucur[r];
            const __half2* vh2 = (const __half2*)&v2[r];
            const __half2 t = __hfma2(uh2[0], vh2[0], __hmul2(uh2[1], vh2[1]));
            float dv = __low2float(t) + __high2float(t);
            dv += __shfl_xor_sync(0xffffffffu, dv, 1);
            dv += __shfl_xor_sync(0xffffffffu, dv, 2);
            if ((lane & 3) == 0) gbuf[w][r * 8 + (lane >> 2)] = dv;
        }
        __syncwarp();

        // softmax over j for the 4 p's (octet-local)
        {
            float lg[2];
            float mx = -1e30f;
#pragma unroll
            for (int i = 0; i < 2; i++) {
                if (i < nj) {
                    lg[i] = gbuf[w][sm_ps * 10 + k8 + i * 8];
                    mx = fmaxf(mx, lg[i]);
                } else lg[i] = -1e30f;
            }
            mx = fmaxf(mx, __shfl_xor_sync(0xffffffffu, mx, 1));
            mx = fmaxf(mx, __shfl_xor_sync(0xffffffffu, mx, 2));
            mx = fmaxf(mx, __shfl_xor_sync(0xffffffffu, mx, 4));
            float e[2], sm = 0.f;
#pragma unroll
            for (int i = 0; i < 2; i++) {
                e[i] = (i < nj) ? __expf(lg[i] - mx) : 0.f;
                sm += e[i];
            }
            sm += __shfl_xor_sync(0xffffffffu, sm, 1);
            sm += __shfl_xor_sync(0xffffffffu, sm, 2);
            sm += __shfl_xor_sync(0xffffffffu, sm, 4);
            const float inv = __fdividef(1.f, sm);
#pragma unroll
            for (int i = 0; i < 2; i++)
                if (i < nj) cbuf[w][sm_ps * 10 + k8 + i * 8] = e[i] * inv;
        }
        __syncwarp();

        // accumulate c * u (packed fp32 FMA)
#pragma unroll
        for (int r = 0; r < 5; r++) {
            const float2 c2 = dup2(cbuf[w][r * 8 + (lane >> 2)]);
            const __half2* uh2 = (const __half2*)&ucur[r];
            sacc[r][0] = ffma2(c2, __half22float2(uh2[0]), sacc[r][0]);
            sacc[r][1] = ffma2(c2, __half22float2(uh2[1]), sacc[r][1]);
        }
        __syncwarp();

#pragma unroll
        for (int r = 0; r < 5; r++) ucur[r] = unxt[r];
    }

    // fold sacc into red[w][jo]: 4 phases by p_sub (conflict-free per phase)
    for (int i = lane; i < JO_; i += 32) red[w][i] = 0.f;
    __syncwarp();
#pragma unroll
    for (int ph = 0; ph < 4; ph++) {
#pragma unroll
        for (int r = 0; r < 5; r++) {
            const int u = r * 32 + lane;
            if (u / 40 == ph) {
                const int qq = (4 * u) % 160;
                red[w][qq + 0] += sacc[r][0].x;
                red[w][qq + 1] += sacc[r][0].y;
                red[w][qq + 2] += sacc[r][1].x;
                red[w][qq + 3] += sacc[r][1].y;
            }
        }
        __syncwarp();
    }
    __syncthreads();

    if (threadIdx.x < JO_) {
        float s = 0.f;
#pragma unroll
        for (int k = 0; k < 8; k++) s += red[k][threadIdx.x];
        atomicAdd(&g_s[SLOT * B_ * JO_ + b * JO_ + threadIdx.x], s);
    }
}

// ---------------------------------------------------------------------------
extern "C" void kernel_launch(void* const* d_in, const int* in_sizes, int n_in,
                              void* d_out, int out_size) {
    const float* x = (const float*)d_in[0];
    const float* W = (const float*)d_in[1];
    if (n_in >= 2 && in_sizes[0] > in_sizes[1]) {
        x = (const float*)d_in[1];
        W = (const float*)d_in[0];
    }
    float* out = (float*)d_out;

    zero_s_kernel<<<60, 256>>>();
    pass0_kernel<<<1024, 256>>>(x, W);
    squash_kernel<<<2, 160>>>(0, nullptr);     // v1 -> g_vh, g_vf
    route_kernel<1><<<2048, 256>>>();          // logits u·v1 -> s2
    squash_kernel<<<2, 160>>>(1, nullptr);     // g_vh = v1+v2
    route_kernel<2><<<2048, 256>>>();          // logits u·(v1+v2) -> s3
    squash_kernel<<<2, 160>>>(2, out);         // v3 -> out
}